// round 1
// baseline (speedup 1.0000x reference)
#include <cuda_runtime.h>

#define T_LEN 1024

typedef unsigned long long u64;

__device__ __forceinline__ float ex2f(float x){ float r; asm("ex2.approx.f32 %0, %1;" : "=f"(r) : "f"(x)); return r; }
__device__ __forceinline__ float rcpf(float x){ float r; asm("rcp.approx.f32 %0, %1;" : "=f"(r) : "f"(x)); return r; }
__device__ __forceinline__ u64 pk2(float a, float b){ u64 r; asm("mov.b64 %0, {%1, %2};" : "=l"(r) : "f"(a), "f"(b)); return r; }
__device__ __forceinline__ void upk2(u64 v, float &a, float &b){ asm("mov.b64 {%0, %1}, %2;" : "=f"(a), "=f"(b) : "l"(v)); }
__device__ __forceinline__ u64 ffma2(u64 a, u64 b, u64 c){ u64 d; asm("fma.rn.f32x2 %0, %1, %2, %3;" : "=l"(d) : "l"(a), "l"(b), "l"(c)); return d; }

// sigmoid(v) where p = -log2(e)*v  : 1/(1+2^p)
__device__ __forceinline__ float sig_p(float p){ return rcpf(1.0f + ex2f(p)); }
// tanh(v) where p = -2*log2(e)*v   : 2/(1+2^p) - 1
__device__ __forceinline__ float tanh_p(float p){ return fmaf(2.0f, rcpf(1.0f + ex2f(p)), -1.0f); }

__global__ void __launch_bounds__(128, 1)
lstm_mlp_kernel(const float* __restrict__ x,
                const float* __restrict__ Wih0, const float* __restrict__ Whh0,
                const float* __restrict__ bih0, const float* __restrict__ bhh0,
                const float* __restrict__ Wih1, const float* __restrict__ Whh1,
                const float* __restrict__ bih1, const float* __restrict__ bhh1,
                const float* __restrict__ W1,   const float* __restrict__ b1,
                const float* __restrict__ W2,   const float* __restrict__ b2,
                float* __restrict__ yout, int B)
{
    int gt = blockIdx.x * blockDim.x + threadIdx.x;
    int b  = gt >> 2;        // batch element (one quad of lanes per element)
    int j  = gt & 3;         // hidden unit owned by this lane
    if (b >= B) return;

    const float SS = -1.4426950408889634f;   // -log2(e)   (sigmoid gates i,f,o)
    const float ST = -2.8853900817779268f;   // -2*log2(e) (tanh: g, c, head)

    const int ri = j, rf = 4 + j, rg = 8 + j, ro = 12 + j;   // rows: i,f,g,o stacked

    // ---- layer0 packed weights: P lane pair = (i,f), Q = (g,o)
    u64 p0x[3], q0x[3], p0h[4], q0h[4];
#pragma unroll
    for (int k = 0; k < 3; ++k) {
        p0x[k] = pk2(SS * Wih0[ri*3+k], SS * Wih0[rf*3+k]);
        q0x[k] = pk2(ST * Wih0[rg*3+k], SS * Wih0[ro*3+k]);
    }
#pragma unroll
    for (int m = 0; m < 4; ++m) {
        p0h[m] = pk2(SS * Whh0[ri*4+m], SS * Whh0[rf*4+m]);
        q0h[m] = pk2(ST * Whh0[rg*4+m], SS * Whh0[ro*4+m]);
    }
    u64 p0b = pk2(SS*(bih0[ri]+bhh0[ri]), SS*(bih0[rf]+bhh0[rf]));
    u64 q0b = pk2(ST*(bih0[rg]+bhh0[rg]), SS*(bih0[ro]+bhh0[ro]));

    // ---- layer1
    u64 p1x[4], q1x[4], p1h[4], q1h[4];
#pragma unroll
    for (int m = 0; m < 4; ++m) {
        p1x[m] = pk2(SS * Wih1[ri*4+m], SS * Wih1[rf*4+m]);
        q1x[m] = pk2(ST * Wih1[rg*4+m], SS * Wih1[ro*4+m]);
        p1h[m] = pk2(SS * Whh1[ri*4+m], SS * Whh1[rf*4+m]);
        q1h[m] = pk2(ST * Whh1[rg*4+m], SS * Whh1[ro*4+m]);
    }
    u64 p1b = pk2(SS*(bih1[ri]+bhh1[ri]), SS*(bih1[rf]+bhh1[rf]));
    u64 q1b = pk2(ST*(bih1[rg]+bhh1[rg]), SS*(bih1[ro]+bhh1[ro]));

    // ---- head (tanh scale folded into W1,b1)
    float w1s0 = ST*W1[j*4+0], w1s1 = ST*W1[j*4+1], w1s2 = ST*W1[j*4+2], w1s3 = ST*W1[j*4+3];
    float b1s = ST*b1[j];
    float w2j = W2[j];
    float b2v = b2[0];

    // ---- state
    float c0 = 0.f, c1 = 0.f, h0 = 0.f, h1 = 0.f;
    u64 z2 = pk2(0.f, 0.f);
    u64 mp0 = z2, mp1 = z2, mp2 = z2, mp3 = z2;   // broadcast-packed h0 (prev step)
    u64 hp0 = z2, hp1 = z2, hp2 = z2, hp3 = z2;   // broadcast-packed h1 (prev step)

    const float4* __restrict__ xr = reinterpret_cast<const float4*>(x + (size_t)b * (3*T_LEN));
    float4* __restrict__ yr = reinterpret_cast<float4*>(yout + (size_t)b * T_LEN);

    const unsigned FULL = 0xffffffffu;

    auto step = [&](float x0, float x1, float x2) -> float {
        // ---------------- layer 0
        u64 P = p0b, Q = q0b;
        u64 xb0 = pk2(x0,x0), xb1 = pk2(x1,x1), xb2 = pk2(x2,x2);
        P = ffma2(p0x[0], xb0, P);  Q = ffma2(q0x[0], xb0, Q);
        P = ffma2(p0x[1], xb1, P);  Q = ffma2(q0x[1], xb1, Q);
        P = ffma2(p0x[2], xb2, P);  Q = ffma2(q0x[2], xb2, Q);
        P = ffma2(p0h[0], mp0, P);  Q = ffma2(q0h[0], mp0, Q);
        P = ffma2(p0h[1], mp1, P);  Q = ffma2(q0h[1], mp1, Q);
        P = ffma2(p0h[2], mp2, P);  Q = ffma2(q0h[2], mp2, Q);
        P = ffma2(p0h[3], mp3, P);  Q = ffma2(q0h[3], mp3, Q);
        float pi, pf, pg, po;
        upk2(P, pi, pf); upk2(Q, pg, po);
        float iv = sig_p(pi), fv = sig_p(pf), gv = tanh_p(pg), ov = sig_p(po);
        c0 = fmaf(fv, c0, iv * gv);
        h0 = ov * tanh_p(ST * c0);
        float n0 = __shfl_sync(FULL, h0, 0, 4);
        float n1 = __shfl_sync(FULL, h0, 1, 4);
        float n2 = __shfl_sync(FULL, h0, 2, 4);
        float n3 = __shfl_sync(FULL, h0, 3, 4);
        mp0 = pk2(n0,n0); mp1 = pk2(n1,n1); mp2 = pk2(n2,n2); mp3 = pk2(n3,n3);
        // ---------------- layer 1
        u64 P1 = p1b, Q1 = q1b;
        P1 = ffma2(p1x[0], mp0, P1);  Q1 = ffma2(q1x[0], mp0, Q1);
        P1 = ffma2(p1x[1], mp1, P1);  Q1 = ffma2(q1x[1], mp1, Q1);
        P1 = ffma2(p1x[2], mp2, P1);  Q1 = ffma2(q1x[2], mp2, Q1);
        P1 = ffma2(p1x[3], mp3, P1);  Q1 = ffma2(q1x[3], mp3, Q1);
        P1 = ffma2(p1h[0], hp0, P1);  Q1 = ffma2(q1h[0], hp0, Q1);
        P1 = ffma2(p1h[1], hp1, P1);  Q1 = ffma2(q1h[1], hp1, Q1);
        P1 = ffma2(p1h[2], hp2, P1);  Q1 = ffma2(q1h[2], hp2, Q1);
        P1 = ffma2(p1h[3], hp3, P1);  Q1 = ffma2(q1h[3], hp3, Q1);
        upk2(P1, pi, pf); upk2(Q1, pg, po);
        iv = sig_p(pi); fv = sig_p(pf); gv = tanh_p(pg); ov = sig_p(po);
        c1 = fmaf(fv, c1, iv * gv);
        h1 = ov * tanh_p(ST * c1);
        float r0 = __shfl_sync(FULL, h1, 0, 4);
        float r1 = __shfl_sync(FULL, h1, 1, 4);
        float r2 = __shfl_sync(FULL, h1, 2, 4);
        float r3 = __shfl_sync(FULL, h1, 3, 4);
        hp0 = pk2(r0,r0); hp1 = pk2(r1,r1); hp2 = pk2(r2,r2); hp3 = pk2(r3,r3);
        // ---------------- head: y = W2 . tanh(W1 h1 + b1) + b2
        float zp = b1s;
        zp = fmaf(w1s0, r0, zp);
        zp = fmaf(w1s1, r1, zp);
        zp = fmaf(w1s2, r2, zp);
        zp = fmaf(w1s3, r3, zp);
        float part = w2j * tanh_p(zp);
        part += __shfl_xor_sync(FULL, part, 1, 4);
        part += __shfl_xor_sync(FULL, part, 2, 4);
        return part + b2v;
    };

#pragma unroll 1
    for (int g4 = 0; g4 < T_LEN/4; ++g4) {
        float4 A  = __ldg(xr + 3*g4 + 0);
        float4 Bv = __ldg(xr + 3*g4 + 1);
        float4 C  = __ldg(xr + 3*g4 + 2);
        float y0 = step(A.x,  A.y,  A.z);
        float y1 = step(A.w,  Bv.x, Bv.y);
        float y2 = step(Bv.z, Bv.w, C.x);
        float y3 = step(C.y,  C.z,  C.w);
        if (j == 0) yr[g4] = make_float4(y0, y1, y2, y3);
    }
}

extern "C" void kernel_launch(void* const* d_in, const int* in_sizes, int n_in,
                              void* d_out, int out_size)
{
    const float* x    = (const float*)d_in[0];
    const float* Wih0 = (const float*)d_in[1];
    const float* Whh0 = (const float*)d_in[2];
    const float* bih0 = (const float*)d_in[3];
    const float* bhh0 = (const float*)d_in[4];
    const float* Wih1 = (const float*)d_in[5];
    const float* Whh1 = (const float*)d_in[6];
    const float* bih1 = (const float*)d_in[7];
    const float* bhh1 = (const float*)d_in[8];
    const float* W1   = (const float*)d_in[9];
    const float* b1   = (const float*)d_in[10];
    const float* W2   = (const float*)d_in[11];
    const float* b2   = (const float*)d_in[12];

    int B = out_size / T_LEN;           // output is [B, T, 1]
    int threads = 4 * B;
    int block = 128;
    int grid = (threads + block - 1) / block;
    lstm_mlp_kernel<<<grid, block>>>(x, Wih0, Whh0, bih0, bhh0,
                                     Wih1, Whh1, bih1, bhh1,
                                     W1, b1, W2, b2,
                                     (float*)d_out, B);
}

// round 3
// speedup vs baseline: 1.1445x; 1.1445x over previous
#include <cuda_runtime.h>

#define T_LEN   1024
#define PHASE_L 16
#define NPH     (T_LEN / PHASE_L)   // 64 phases
#define QPB     32                  // batch elements (quads) per block
#define BLOCKT  256                 // 4 producer warps + 4 consumer warps

typedef unsigned long long u64;

__device__ __forceinline__ float ex2f(float x){ float r; asm("ex2.approx.f32 %0, %1;" : "=f"(r) : "f"(x)); return r; }
__device__ __forceinline__ float rcpf(float x){ float r; asm("rcp.approx.f32 %0, %1;" : "=f"(r) : "f"(x)); return r; }
__device__ __forceinline__ u64 pk2(float a, float b){ u64 r; asm("mov.b64 %0, {%1, %2};" : "=l"(r) : "f"(a), "f"(b)); return r; }
__device__ __forceinline__ void upk2(u64 v, float &a, float &b){ asm("mov.b64 {%0, %1}, %2;" : "=f"(a), "=f"(b) : "l"(v)); }
__device__ __forceinline__ u64 ffma2(u64 a, u64 b, u64 c){ u64 d; asm("fma.rn.f32x2 %0, %1, %2, %3;" : "=l"(d) : "l"(a), "l"(b), "l"(c)); return d; }

// sigmoid(v) where p = -log2(e)*v  : 1/(1+2^p)
__device__ __forceinline__ float sig_p(float p){ return rcpf(1.0f + ex2f(p)); }
// tanh(v) where p = -2*log2(e)*v   : 2/(1+2^p) - 1
__device__ __forceinline__ float tanh_p(float p){ return fmaf(2.0f, rcpf(1.0f + ex2f(p)), -1.0f); }

__global__ void __launch_bounds__(BLOCKT, 1)
lstm_pipe_kernel(const float* __restrict__ x,
                 const float* __restrict__ Wih0, const float* __restrict__ Whh0,
                 const float* __restrict__ bih0, const float* __restrict__ bhh0,
                 const float* __restrict__ Wih1, const float* __restrict__ Whh1,
                 const float* __restrict__ bih1, const float* __restrict__ bhh1,
                 const float* __restrict__ W1,   const float* __restrict__ b1,
                 const float* __restrict__ W2,   const float* __restrict__ b2,
                 float* __restrict__ yout, int B)
{
    // double-buffered h0 hand-off: [buf][step][quad], step-major so a warp's
    // 32 lanes (8 quads x 4 units) hit 32 consecutive banks on STS.
    __shared__ float4 h0buf[2][PHASE_L][QPB];

    const int tid    = threadIdx.x;
    const bool isProd = (tid < 128);     // warps 0-3 = layer0, warps 4-7 = layer1+head
    const int l    = tid & 127;
    const int quad = l >> 2;             // 0..31: which batch element in this block
    const int j    = l & 3;              // hidden unit owned by this lane
    const int b    = blockIdx.x * QPB + quad;
    const bool alive = (b < B);

    const float SS = -1.4426950408889634f;   // -log2(e)    (sigmoid pre-scale)
    const float ST = -2.8853900817779268f;   // -2*log2(e)  (tanh pre-scale)
    const int ri = j, rf = 4 + j, rg = 8 + j, ro = 12 + j;

    // ---- unified packed gate weights for THIS thread's layer.
    // P lane pair = (i,f) [sigmoid], Q = (g,o) [tanh, sigmoid]
    u64 px[4], qx[4], ph[4], qh[4], pb, qb;
    float w1s0=0.f, w1s1=0.f, w1s2=0.f, w1s3=0.f, b1s=0.f, w2j=0.f, b2v=0.f;

    if (isProd) {
#pragma unroll
        for (int k = 0; k < 3; ++k) {
            px[k] = pk2(SS * Wih0[ri*3+k], SS * Wih0[rf*3+k]);
            qx[k] = pk2(ST * Wih0[rg*3+k], SS * Wih0[ro*3+k]);
        }
        px[3] = 0ull; qx[3] = 0ull;
#pragma unroll
        for (int m = 0; m < 4; ++m) {
            ph[m] = pk2(SS * Whh0[ri*4+m], SS * Whh0[rf*4+m]);
            qh[m] = pk2(ST * Whh0[rg*4+m], SS * Whh0[ro*4+m]);
        }
        pb = pk2(SS*(bih0[ri]+bhh0[ri]), SS*(bih0[rf]+bhh0[rf]));
        qb = pk2(ST*(bih0[rg]+bhh0[rg]), SS*(bih0[ro]+bhh0[ro]));
    } else {
#pragma unroll
        for (int m = 0; m < 4; ++m) {
            px[m] = pk2(SS * Wih1[ri*4+m], SS * Wih1[rf*4+m]);
            qx[m] = pk2(ST * Wih1[rg*4+m], SS * Wih1[ro*4+m]);
            ph[m] = pk2(SS * Whh1[ri*4+m], SS * Whh1[rf*4+m]);
            qh[m] = pk2(ST * Whh1[rg*4+m], SS * Whh1[ro*4+m]);
        }
        pb = pk2(SS*(bih1[ri]+bhh1[ri]), SS*(bih1[rf]+bhh1[rf]));
        qb = pk2(ST*(bih1[rg]+bhh1[rg]), SS*(bih1[ro]+bhh1[ro]));
        // head (tanh scale folded into W1,b1)
        w1s0 = ST*W1[j*4+0]; w1s1 = ST*W1[j*4+1]; w1s2 = ST*W1[j*4+2]; w1s3 = ST*W1[j*4+3];
        b1s  = ST*b1[j];
        w2j  = W2[j];
        b2v  = b2[0];
    }

    // ---- recurrent state
    float cst = 0.f, hst = 0.f;
    const u64 z2 = pk2(0.f, 0.f);
    u64 hp0 = z2, hp1 = z2, hp2 = z2, hp3 = z2;  // broadcast-packed own-layer h(t-1)
    float rr0 = 0.f, rr1 = 0.f, rr2 = 0.f, rr3 = 0.f;

    const float4* __restrict__ xr = reinterpret_cast<const float4*>(x + (size_t)b * (3*T_LEN));
    float4* __restrict__ yr4 = reinterpret_cast<float4*>(yout + (size_t)b * T_LEN);

    const unsigned FULL = 0xffffffffu;

    // One LSTM cell step for this thread's layer. Inputs are lane-pair packed.
    auto cell = [&](u64 in0, u64 in1, u64 in2, u64 in3) {
        u64 P = pb, Q = qb;
        P = ffma2(px[0], in0, P);  Q = ffma2(qx[0], in0, Q);
        P = ffma2(px[1], in1, P);  Q = ffma2(qx[1], in1, Q);
        P = ffma2(px[2], in2, P);  Q = ffma2(qx[2], in2, Q);
        P = ffma2(px[3], in3, P);  Q = ffma2(qx[3], in3, Q);
        P = ffma2(ph[0], hp0, P);  Q = ffma2(qh[0], hp0, Q);
        P = ffma2(ph[1], hp1, P);  Q = ffma2(qh[1], hp1, Q);
        P = ffma2(ph[2], hp2, P);  Q = ffma2(qh[2], hp2, Q);
        P = ffma2(ph[3], hp3, P);  Q = ffma2(qh[3], hp3, Q);
        float pi, pf, pg, po;
        upk2(P, pi, pf); upk2(Q, pg, po);
        float iv = sig_p(pi), fv = sig_p(pf), gv = tanh_p(pg), ov = sig_p(po);
        cst = fmaf(fv, cst, iv * gv);
        hst = ov * tanh_p(ST * cst);
        rr0 = __shfl_sync(FULL, hst, 0, 4);
        rr1 = __shfl_sync(FULL, hst, 1, 4);
        rr2 = __shfl_sync(FULL, hst, 2, 4);
        rr3 = __shfl_sync(FULL, hst, 3, 4);
        hp0 = pk2(rr0, rr0); hp1 = pk2(rr1, rr1);
        hp2 = pk2(rr2, rr2); hp3 = pk2(rr3, rr3);
    };

#pragma unroll 1
    for (int k = 0; k <= NPH; ++k) {
        if (isProd) {
            if (k < NPH) {
                // layer0: 16 time steps, t = k*16 + g*4 + s
#pragma unroll
                for (int g = 0; g < 4; ++g) {
                    float4 A  = alive ? __ldg(xr + k*12 + g*3 + 0) : make_float4(0.f,0.f,0.f,0.f);
                    float4 Bv = alive ? __ldg(xr + k*12 + g*3 + 1) : make_float4(0.f,0.f,0.f,0.f);
                    float4 C  = alive ? __ldg(xr + k*12 + g*3 + 2) : make_float4(0.f,0.f,0.f,0.f);
                    float xs[4][3] = {
                        {A.x,  A.y,  A.z },
                        {A.w,  Bv.x, Bv.y},
                        {Bv.z, Bv.w, C.x },
                        {C.y,  C.z,  C.w },
                    };
#pragma unroll
                    for (int s = 0; s < 4; ++s) {
                        cell(pk2(xs[s][0], xs[s][0]),
                             pk2(xs[s][1], xs[s][1]),
                             pk2(xs[s][2], xs[s][2]),
                             z2);
                        ((float*)&h0buf[k & 1][g*4 + s][quad])[j] = hst;
                    }
                }
            }
        } else {
            if (k >= 1) {
                // layer1 + head for phase k-1
#pragma unroll
                for (int g = 0; g < 4; ++g) {
                    float yv[4];
#pragma unroll
                    for (int s = 0; s < 4; ++s) {
                        float4 hv = h0buf[(k-1) & 1][g*4 + s][quad];
                        cell(pk2(hv.x, hv.x), pk2(hv.y, hv.y),
                             pk2(hv.z, hv.z), pk2(hv.w, hv.w));
                        // head: y = W2 . tanh(W1 h1 + b1) + b2 (off the recurrence path)
                        float zp = b1s;
                        zp = fmaf(w1s0, rr0, zp);
                        zp = fmaf(w1s1, rr1, zp);
                        zp = fmaf(w1s2, rr2, zp);
                        zp = fmaf(w1s3, rr3, zp);
                        float part = w2j * tanh_p(zp);
                        part += __shfl_xor_sync(FULL, part, 1, 4);
                        part += __shfl_xor_sync(FULL, part, 2, 4);
                        yv[s] = part + b2v;
                    }
                    if (j == 0 && alive)
                        yr4[(k-1)*4 + g] = make_float4(yv[0], yv[1], yv[2], yv[3]);
                }
            }
        }
        __syncthreads();
    }
}

extern "C" void kernel_launch(void* const* d_in, const int* in_sizes, int n_in,
                              void* d_out, int out_size)
{
    const float* x    = (const float*)d_in[0];
    const float* Wih0 = (const float*)d_in[1];
    const float* Whh0 = (const float*)d_in[2];
    const float* bih0 = (const float*)d_in[3];
    const float* bhh0 = (const float*)d_in[4];
    const float* Wih1 = (const float*)d_in[5];
    const float* Whh1 = (const float*)d_in[6];
    const float* bih1 = (const float*)d_in[7];
    const float* bhh1 = (const float*)d_in[8];
    const float* W1   = (const float*)d_in[9];
    const float* b1   = (const float*)d_in[10];
    const float* W2   = (const float*)d_in[11];
    const float* b2   = (const float*)d_in[12];

    int B = out_size / T_LEN;                 // output is [B, T, 1]
    int grid = (B + QPB - 1) / QPB;           // 128 blocks for B=4096
    lstm_pipe_kernel<<<grid, BLOCKT>>>(x, Wih0, Whh0, bih0, bhh0,
                                       Wih1, Whh1, bih1, bhh1,
                                       W1, b1, W2, b2,
                                       (float*)d_out, B);
}

// round 6
// speedup vs baseline: 2.1579x; 1.8854x over previous
#include <cuda_runtime.h>

#define T_LEN   1024
#define PHASE_L 16
#define NPH     (T_LEN / PHASE_L)   // 64 phases
#define QPB     32                  // batch elements (quads) per block
#define BLOCKT  256                 // 4 producer warps (L0) + 4 consumer warps (L1+head)

typedef unsigned long long u64;

__device__ __forceinline__ float tanhaf(float x){ float r; asm("tanh.approx.f32 %0, %1;" : "=f"(r) : "f"(x)); return r; }
__device__ __forceinline__ u64 pk2(float a, float b){ u64 r; asm("mov.b64 %0, {%1, %2};" : "=l"(r) : "f"(a), "f"(b)); return r; }
__device__ __forceinline__ void upk2(u64 v, float &a, float &b){ asm("mov.b64 {%0, %1}, %2;" : "=f"(a), "=f"(b) : "l"(v)); }
__device__ __forceinline__ u64 ffma2(u64 a, u64 b, u64 c){ u64 d; asm("fma.rn.f32x2 %0, %1, %2, %3;" : "=l"(d) : "l"(a), "l"(b), "l"(c)); return d; }

__global__ void __launch_bounds__(BLOCKT, 1)
lstm_pipe_kernel(const float* __restrict__ x,
                 const float* __restrict__ Wih0, const float* __restrict__ Whh0,
                 const float* __restrict__ bih0, const float* __restrict__ bhh0,
                 const float* __restrict__ Wih1, const float* __restrict__ Whh1,
                 const float* __restrict__ bih1, const float* __restrict__ bhh1,
                 const float* __restrict__ W1,   const float* __restrict__ b1,
                 const float* __restrict__ W2,   const float* __restrict__ b2,
                 float* __restrict__ yout, int B)
{
    // double-buffered h0 hand-off: [buf][step][quad]; producer's 32 lanes write
    // 32 consecutive floats per step (conflict-free), consumer LDS.128 broadcasts.
    __shared__ float4 h0buf[2][PHASE_L][QPB];

    const int tid     = threadIdx.x;
    const bool isProd = (tid < 128);
    const int l    = tid & 127;
    const int quad = l >> 2;
    const int j    = l & 3;
    const int b    = blockIdx.x * QPB + quad;
    const bool alive = (b < B);

    // sigmoid(v) = 0.5 + 0.5*tanh(v/2): fold the 1/2 pre-scale into i,f,o rows.
    const int ri = j, rf = 4 + j, rg = 8 + j, ro = 12 + j;

    // Packed gate weights: P lane pair = (i,f) [half-scaled], Q = (g,o) [g plain, o half].
    // h-recurrence weights permuted so column index = j ^ m (xor-shuffle broadcast).
    u64 px[4], qx[4], ph[4], qh[4], pb, qb;
    float w1p0=0.f, w1p1=0.f, w1p2=0.f, w1p3=0.f, b1s=0.f, w2j=0.f, b2c=0.f;

    if (isProd) {
#pragma unroll
        for (int k = 0; k < 3; ++k) {
            px[k] = pk2(0.5f * Wih0[ri*3+k], 0.5f * Wih0[rf*3+k]);
            qx[k] = pk2(       Wih0[rg*3+k], 0.5f * Wih0[ro*3+k]);
        }
        px[3] = 0ull; qx[3] = 0ull;
#pragma unroll
        for (int m = 0; m < 4; ++m) {
            int cm = j ^ m;
            ph[m] = pk2(0.5f * Whh0[ri*4+cm], 0.5f * Whh0[rf*4+cm]);
            qh[m] = pk2(       Whh0[rg*4+cm], 0.5f * Whh0[ro*4+cm]);
        }
        pb = pk2(0.5f*(bih0[ri]+bhh0[ri]), 0.5f*(bih0[rf]+bhh0[rf]));
        qb = pk2(     (bih0[rg]+bhh0[rg]), 0.5f*(bih0[ro]+bhh0[ro]));
    } else {
#pragma unroll
        for (int m = 0; m < 4; ++m) {
            int cm = j ^ m;
            // x-part (h0 from smem float4): natural column order m
            px[m] = pk2(0.5f * Wih1[ri*4+m], 0.5f * Wih1[rf*4+m]);
            qx[m] = pk2(       Wih1[rg*4+m], 0.5f * Wih1[ro*4+m]);
            // own-recurrence: xor-permuted
            ph[m] = pk2(0.5f * Whh1[ri*4+cm], 0.5f * Whh1[rf*4+cm]);
            qh[m] = pk2(       Whh1[rg*4+cm], 0.5f * Whh1[ro*4+cm]);
        }
        pb = pk2(0.5f*(bih1[ri]+bhh1[ri]), 0.5f*(bih1[rf]+bhh1[rf]));
        qb = pk2(     (bih1[rg]+bhh1[rg]), 0.5f*(bih1[ro]+bhh1[ro]));
        // head (xor-permuted to reuse the cell's shfl results)
        w1p0 = W1[j*4 + (j^0)]; w1p1 = W1[j*4 + (j^1)];
        w1p2 = W1[j*4 + (j^2)]; w1p3 = W1[j*4 + (j^3)];
        b1s  = b1[j];
        w2j  = W2[j];
        b2c  = b2[0];
    }

    float cst = 0.f, hst = 0.f;
    float ps1 = 0.f, ps2 = 0.f, ps3 = 0.f;  // shfl'd h(t-1) (for consumer head lag)
    float pown = 0.f;                       // own h(t-1)

    const float4* __restrict__ xr = reinterpret_cast<const float4*>(x + (size_t)b * (3*T_LEN));
    float* __restrict__ yr = yout + (size_t)b * T_LEN;

    const unsigned FULL = 0xffffffffu;

    // One LSTM cell step: Px/Qx carry bias + input contributions (precomputed).
    auto cell = [&](u64 Px, u64 Qx) {
        pown = hst;
        u64 hb = pk2(hst, hst);
        float s1 = __shfl_xor_sync(FULL, hst, 1, 4);
        float s2 = __shfl_xor_sync(FULL, hst, 2, 4);
        float s3 = __shfl_xor_sync(FULL, hst, 3, 4);
        u64 P = ffma2(ph[0], hb, Px);
        u64 Q = ffma2(qh[0], hb, Qx);
        u64 v1 = pk2(s1, s1), v2 = pk2(s2, s2), v3 = pk2(s3, s3);
        P = ffma2(ph[1], v1, P);  Q = ffma2(qh[1], v1, Q);
        P = ffma2(ph[2], v2, P);  Q = ffma2(qh[2], v2, Q);
        P = ffma2(ph[3], v3, P);  Q = ffma2(qh[3], v3, Q);
        float pi, pf, pg, po;
        upk2(P, pi, pf); upk2(Q, pg, po);
        float ti = tanhaf(pi), tf = tanhaf(pf), tg = tanhaf(pg), to = tanhaf(po);
        float iv = fmaf(0.5f, ti, 0.5f);
        float fv = fmaf(0.5f, tf, 0.5f);
        float ov = fmaf(0.5f, to, 0.5f);
        cst = fmaf(fv, cst, iv * tg);
        hst = ov * tanhaf(cst);
        ps1 = s1; ps2 = s2; ps3 = s3;
    };

    // Head for the step whose h1 broadcast = (own, s1, s2, s3). Off the recurrence path.
    auto head = [&](float own, float s1, float s2, float s3) -> float {
        float zp = b1s;
        zp = fmaf(w1p0, own, zp);
        zp = fmaf(w1p1, s1, zp);
        zp = fmaf(w1p2, s2, zp);
        zp = fmaf(w1p3, s3, zp);
        float part = w2j * tanhaf(zp);
        part += __shfl_xor_sync(FULL, part, 1, 4);
        part += __shfl_xor_sync(FULL, part, 2, 4);
        return part + b2c;
    };

#pragma unroll 1
    for (int k = 0; k <= NPH; ++k) {
        if (isProd) {
            if (k < NPH) {
#pragma unroll
                for (int g = 0; g < 4; ++g) {
                    float4 A  = alive ? __ldg(xr + k*12 + g*3 + 0) : make_float4(0.f,0.f,0.f,0.f);
                    float4 Bv = alive ? __ldg(xr + k*12 + g*3 + 1) : make_float4(0.f,0.f,0.f,0.f);
                    float4 C  = alive ? __ldg(xr + k*12 + g*3 + 2) : make_float4(0.f,0.f,0.f,0.f);
                    float xs[4][3] = {
                        {A.x,  A.y,  A.z },
                        {A.w,  Bv.x, Bv.y},
                        {Bv.z, Bv.w, C.x },
                        {C.y,  C.z,  C.w },
                    };
                    u64 Pxs[4], Qxs[4];
#pragma unroll
                    for (int s = 0; s < 4; ++s) {
                        u64 x0 = pk2(xs[s][0], xs[s][0]);
                        u64 x1 = pk2(xs[s][1], xs[s][1]);
                        u64 x2 = pk2(xs[s][2], xs[s][2]);
                        u64 Px = ffma2(px[0], x0, pb);
                        u64 Qx = ffma2(qx[0], x0, qb);
                        Px = ffma2(px[1], x1, Px);  Qx = ffma2(qx[1], x1, Qx);
                        Px = ffma2(px[2], x2, Px);  Qx = ffma2(qx[2], x2, Qx);
                        Pxs[s] = Px; Qxs[s] = Qx;
                    }
#pragma unroll
                    for (int s = 0; s < 4; ++s) {
                        cell(Pxs[s], Qxs[s]);
                        ((float*)&h0buf[k & 1][g*4 + s][quad])[j] = hst;
                    }
                }
            }
        } else {
            if (k >= 1) {
                const int p = k - 1;
#pragma unroll
                for (int g = 0; g < 4; ++g) {
                    float4 hv[4];
#pragma unroll
                    for (int s = 0; s < 4; ++s) hv[s] = h0buf[p & 1][g*4 + s][quad];
                    u64 Pxs[4], Qxs[4];
#pragma unroll
                    for (int s = 0; s < 4; ++s) {
                        u64 x0 = pk2(hv[s].x, hv[s].x);
                        u64 x1 = pk2(hv[s].y, hv[s].y);
                        u64 x2 = pk2(hv[s].z, hv[s].z);
                        u64 x3 = pk2(hv[s].w, hv[s].w);
                        u64 Px = ffma2(px[0], x0, pb);
                        u64 Qx = ffma2(qx[0], x0, qb);
                        Px = ffma2(px[1], x1, Px);  Qx = ffma2(qx[1], x1, Qx);
                        Px = ffma2(px[2], x2, Px);  Qx = ffma2(qx[2], x2, Qx);
                        Px = ffma2(px[3], x3, Px);  Qx = ffma2(qx[3], x3, Qx);
                        Pxs[s] = Px; Qxs[s] = Qx;
                    }
#pragma unroll
                    for (int s = 0; s < 4; ++s) {
                        const int t = p*PHASE_L + g*4 + s;   // global step of THIS cell
                        cell(Pxs[s], Qxs[s]);
                        // cell(t) shfl'd h1(t-1): finish head for step t-1
                        if (t > 0) {
                            float yv = head(pown, ps1, ps2, ps3);
                            if (j == 0 && alive) yr[t - 1] = yv;
                        }
                    }
                }
            }
        }
        __syncthreads();
    }

    // last pending head (t = 1023): broadcast the final hst
    if (!isProd) {
        float s1 = __shfl_xor_sync(FULL, hst, 1, 4);
        float s2 = __shfl_xor_sync(FULL, hst, 2, 4);
        float s3 = __shfl_xor_sync(FULL, hst, 3, 4);
        float yv = head(hst, s1, s2, s3);
        if (j == 0 && alive) yr[T_LEN - 1] = yv;
    }
}

extern "C" void kernel_launch(void* const* d_in, const int* in_sizes, int n_in,
                              void* d_out, int out_size)
{
    const float* x    = (const float*)d_in[0];
    const float* Wih0 = (const float*)d_in[1];
    const float* Whh0 = (const float*)d_in[2];
    const float* bih0 = (const float*)d_in[3];
    const float* bhh0 = (const float*)d_in[4];
    const float* Wih1 = (const float*)d_in[5];
    const float* Whh1 = (const float*)d_in[6];
    const float* bih1 = (const float*)d_in[7];
    const float* bhh1 = (const float*)d_in[8];
    const float* W1   = (const float*)d_in[9];
    const float* b1   = (const float*)d_in[10];
    const float* W2   = (const float*)d_in[11];
    const float* b2   = (const float*)d_in[12];

    int B = out_size / T_LEN;                 // output is [B, T, 1]
    int grid = (B + QPB - 1) / QPB;           // 128 blocks for B=4096
    lstm_pipe_kernel<<<grid, BLOCKT>>>(x, Wih0, Whh0, bih0, bhh0,
                                       Wih1, Whh1, bih1, bhh1,
                                       W1, b1, W2, b2,
                                       (float*)d_out, B);
}

// round 7
// speedup vs baseline: 2.3193x; 1.0748x over previous
#include <cuda_runtime.h>

#define T_LEN   1024
#define PHASE_L 16
#define NPH     (T_LEN / PHASE_L)   // 64 phases
#define NGRP    (T_LEN / 4)         // 256 4-step groups
#define QPB     32                  // batch elements (quads) per block
#define BLOCKT  256                 // 4 producer warps (L0) + 4 consumer warps (L1+head)

typedef unsigned long long u64;

__device__ __forceinline__ float tanhaf(float x){ float r; asm("tanh.approx.f32 %0, %1;" : "=f"(r) : "f"(x)); return r; }
__device__ __forceinline__ u64 pk2(float a, float b){ u64 r; asm("mov.b64 %0, {%1, %2};" : "=l"(r) : "f"(a), "f"(b)); return r; }
__device__ __forceinline__ void upk2(u64 v, float &a, float &b){ asm("mov.b64 {%0, %1}, %2;" : "=f"(a), "=f"(b) : "l"(v)); }
__device__ __forceinline__ u64 ffma2(u64 a, u64 b, u64 c){ u64 d; asm("fma.rn.f32x2 %0, %1, %2, %3;" : "=l"(d) : "l"(a), "l"(b), "l"(c)); return d; }

__global__ void __launch_bounds__(BLOCKT, 1)
lstm_pipe_kernel(const float* __restrict__ x,
                 const float* __restrict__ Wih0, const float* __restrict__ Whh0,
                 const float* __restrict__ bih0, const float* __restrict__ bhh0,
                 const float* __restrict__ Wih1, const float* __restrict__ Whh1,
                 const float* __restrict__ bih1, const float* __restrict__ bhh1,
                 const float* __restrict__ W1,   const float* __restrict__ b1,
                 const float* __restrict__ W2,   const float* __restrict__ b2,
                 float* __restrict__ yout, int B)
{
    // double-buffered h0 hand-off: [buf][step][quad]; producer's 32 lanes write
    // 32 consecutive floats per step (conflict-free), consumer LDS.128 broadcasts.
    __shared__ float4 h0buf[2][PHASE_L][QPB];

    const int tid     = threadIdx.x;
    const bool isProd = (tid < 128);
    const int l    = tid & 127;
    const int quad = l >> 2;
    const int j    = l & 3;
    const int b    = blockIdx.x * QPB + quad;
    const bool alive = (b < B);

    // sigmoid(v) = 0.5 + 0.5*tanh(v/2): fold the 1/2 pre-scale into i,f,o rows.
    const int ri = j, rf = 4 + j, rg = 8 + j, ro = 12 + j;

    // Packed gate weights: P lane pair = (i,f) [half-scaled], Q = (g,o) [g plain, o half].
    // h-recurrence weights permuted so column index = j ^ m (xor-shuffle broadcast).
    u64 px[4], qx[4], ph[4], qh[4], pb, qb;
    float w1p0=0.f, w1p1=0.f, w1p2=0.f, w1p3=0.f, b1s=0.f, w2j=0.f, b2c=0.f;

    if (isProd) {
#pragma unroll
        for (int k = 0; k < 3; ++k) {
            px[k] = pk2(0.5f * Wih0[ri*3+k], 0.5f * Wih0[rf*3+k]);
            qx[k] = pk2(       Wih0[rg*3+k], 0.5f * Wih0[ro*3+k]);
        }
        px[3] = 0ull; qx[3] = 0ull;
#pragma unroll
        for (int m = 0; m < 4; ++m) {
            int cm = j ^ m;
            ph[m] = pk2(0.5f * Whh0[ri*4+cm], 0.5f * Whh0[rf*4+cm]);
            qh[m] = pk2(       Whh0[rg*4+cm], 0.5f * Whh0[ro*4+cm]);
        }
        pb = pk2(0.5f*(bih0[ri]+bhh0[ri]), 0.5f*(bih0[rf]+bhh0[rf]));
        qb = pk2(     (bih0[rg]+bhh0[rg]), 0.5f*(bih0[ro]+bhh0[ro]));
    } else {
#pragma unroll
        for (int m = 0; m < 4; ++m) {
            int cm = j ^ m;
            // x-part (h0 from smem float4): natural column order m
            px[m] = pk2(0.5f * Wih1[ri*4+m], 0.5f * Wih1[rf*4+m]);
            qx[m] = pk2(       Wih1[rg*4+m], 0.5f * Wih1[ro*4+m]);
            // own-recurrence: xor-permuted
            ph[m] = pk2(0.5f * Whh1[ri*4+cm], 0.5f * Whh1[rf*4+cm]);
            qh[m] = pk2(       Whh1[rg*4+cm], 0.5f * Whh1[ro*4+cm]);
        }
        pb = pk2(0.5f*(bih1[ri]+bhh1[ri]), 0.5f*(bih1[rf]+bhh1[rf]));
        qb = pk2(     (bih1[rg]+bhh1[rg]), 0.5f*(bih1[ro]+bhh1[ro]));
        // head (xor-permuted to reuse the cell's shfl results)
        w1p0 = W1[j*4 + (j^0)]; w1p1 = W1[j*4 + (j^1)];
        w1p2 = W1[j*4 + (j^2)]; w1p3 = W1[j*4 + (j^3)];
        b1s  = b1[j];
        w2j  = W2[j];
        b2c  = b2[0];
    }

    float cst = 0.f, hst = 0.f;
    float ps1 = 0.f, ps2 = 0.f, ps3 = 0.f;  // shfl'd h(t-1) (for consumer head lag)
    float pown = 0.f;                       // own h(t-1)

    const float4* __restrict__ xr = reinterpret_cast<const float4*>(x + (size_t)b * (3*T_LEN));
    float* __restrict__ yr = yout + (size_t)b * T_LEN;

    const unsigned FULL = 0xffffffffu;

    // One LSTM cell step: Px/Qx carry bias + input contributions (precomputed).
    auto cell = [&](u64 Px, u64 Qx) {
        pown = hst;
        u64 hb = pk2(hst, hst);
        float s1 = __shfl_xor_sync(FULL, hst, 1, 4);
        float s2 = __shfl_xor_sync(FULL, hst, 2, 4);
        float s3 = __shfl_xor_sync(FULL, hst, 3, 4);
        u64 P = ffma2(ph[0], hb, Px);
        u64 Q = ffma2(qh[0], hb, Qx);
        u64 v1 = pk2(s1, s1), v2 = pk2(s2, s2), v3 = pk2(s3, s3);
        P = ffma2(ph[1], v1, P);  Q = ffma2(qh[1], v1, Q);
        P = ffma2(ph[2], v2, P);  Q = ffma2(qh[2], v2, Q);
        P = ffma2(ph[3], v3, P);  Q = ffma2(qh[3], v3, Q);
        float pi, pf, pg, po;
        upk2(P, pi, pf); upk2(Q, pg, po);
        float ti = tanhaf(pi), tf = tanhaf(pf), tg = tanhaf(pg), to = tanhaf(po);
        float iv = fmaf(0.5f, ti, 0.5f);
        float fv = fmaf(0.5f, tf, 0.5f);
        float ov = fmaf(0.5f, to, 0.5f);
        cst = fmaf(fv, cst, iv * tg);
        hst = ov * tanhaf(cst);
        ps1 = s1; ps2 = s2; ps3 = s3;
    };

    // Head for the step whose h1 broadcast = (own, s1, s2, s3). Off the recurrence path.
    auto head = [&](float own, float s1, float s2, float s3) -> float {
        float zp = b1s;
        zp = fmaf(w1p0, own, zp);
        zp = fmaf(w1p1, s1, zp);
        zp = fmaf(w1p2, s2, zp);
        zp = fmaf(w1p3, s3, zp);
        float part = w2j * tanhaf(zp);
        part += __shfl_xor_sync(FULL, part, 1, 4);
        part += __shfl_xor_sync(FULL, part, 2, 4);
        return part + b2c;
    };

    // Producer: registers holding the CURRENT 4-step group of x (prefetched).
    float4 curA, curB, curC;
    if (isProd) {
        if (alive) {
            curA = __ldg(xr + 0); curB = __ldg(xr + 1); curC = __ldg(xr + 2);
        } else {
            curA = curB = curC = make_float4(0.f,0.f,0.f,0.f);
        }
    }

#pragma unroll 1
    for (int k = 0; k <= NPH; ++k) {
        if (isProd) {
            if (k < NPH) {
#pragma unroll
                for (int g = 0; g < 4; ++g) {
                    // ---- prefetch next group's x (hidden behind this group's 4 cells)
                    const int G = k*4 + g;
                    const int Gn = (G + 1 < NGRP) ? (G + 1) : G;
                    float4 nA, nB, nC;
                    if (alive) {
                        nA = __ldg(xr + 3*Gn + 0);
                        nB = __ldg(xr + 3*Gn + 1);
                        nC = __ldg(xr + 3*Gn + 2);
                    } else {
                        nA = nB = nC = make_float4(0.f,0.f,0.f,0.f);
                    }
                    // ---- gate input contributions for the 4 steps of this group
                    float xs[4][3] = {
                        {curA.x, curA.y, curA.z},
                        {curA.w, curB.x, curB.y},
                        {curB.z, curB.w, curC.x},
                        {curC.y, curC.z, curC.w},
                    };
                    u64 Pxs[4], Qxs[4];
#pragma unroll
                    for (int s = 0; s < 4; ++s) {
                        u64 x0 = pk2(xs[s][0], xs[s][0]);
                        u64 x1 = pk2(xs[s][1], xs[s][1]);
                        u64 x2 = pk2(xs[s][2], xs[s][2]);
                        u64 Px = ffma2(px[0], x0, pb);
                        u64 Qx = ffma2(qx[0], x0, qb);
                        Px = ffma2(px[1], x1, Px);  Qx = ffma2(qx[1], x1, Qx);
                        Px = ffma2(px[2], x2, Px);  Qx = ffma2(qx[2], x2, Qx);
                        Pxs[s] = Px; Qxs[s] = Qx;
                    }
#pragma unroll
                    for (int s = 0; s < 4; ++s) {
                        cell(Pxs[s], Qxs[s]);
                        ((float*)&h0buf[k & 1][g*4 + s][quad])[j] = hst;
                    }
                    curA = nA; curB = nB; curC = nC;
                }
            }
        } else {
            if (k >= 1) {
                const int p = k - 1;
                // prefetch group 0 of this phase
                float4 hv[4], hvn[4];
#pragma unroll
                for (int s = 0; s < 4; ++s) hv[s] = h0buf[p & 1][s][quad];
#pragma unroll
                for (int g = 0; g < 4; ++g) {
                    // prefetch next group's h0 (within this phase's buffer)
                    if (g < 3) {
#pragma unroll
                        for (int s = 0; s < 4; ++s) hvn[s] = h0buf[p & 1][(g+1)*4 + s][quad];
                    }
                    u64 Pxs[4], Qxs[4];
#pragma unroll
                    for (int s = 0; s < 4; ++s) {
                        u64 x0 = pk2(hv[s].x, hv[s].x);
                        u64 x1 = pk2(hv[s].y, hv[s].y);
                        u64 x2 = pk2(hv[s].z, hv[s].z);
                        u64 x3 = pk2(hv[s].w, hv[s].w);
                        u64 Px = ffma2(px[0], x0, pb);
                        u64 Qx = ffma2(qx[0], x0, qb);
                        Px = ffma2(px[1], x1, Px);  Qx = ffma2(qx[1], x1, Qx);
                        Px = ffma2(px[2], x2, Px);  Qx = ffma2(qx[2], x2, Qx);
                        Px = ffma2(px[3], x3, Px);  Qx = ffma2(qx[3], x3, Qx);
                        Pxs[s] = Px; Qxs[s] = Qx;
                    }
#pragma unroll
                    for (int s = 0; s < 4; ++s) {
                        const int t = p*PHASE_L + g*4 + s;   // global step of THIS cell
                        cell(Pxs[s], Qxs[s]);
                        // cell(t) shfl'd h1(t-1): finish head for step t-1
                        if (t > 0) {
                            float yv = head(pown, ps1, ps2, ps3);
                            if (j == 0 && alive) yr[t - 1] = yv;
                        }
                    }
#pragma unroll
                    for (int s = 0; s < 4; ++s) hv[s] = hvn[s];
                }
            }
        }
        __syncthreads();
    }

    // last pending head (t = 1023): broadcast the final hst
    if (!isProd) {
        float s1 = __shfl_xor_sync(FULL, hst, 1, 4);
        float s2 = __shfl_xor_sync(FULL, hst, 2, 4);
        float s3 = __shfl_xor_sync(FULL, hst, 3, 4);
        float yv = head(hst, s1, s2, s3);
        if (j == 0 && alive) yr[T_LEN - 1] = yv;
    }
}

extern "C" void kernel_launch(void* const* d_in, const int* in_sizes, int n_in,
                              void* d_out, int out_size)
{
    const float* x    = (const float*)d_in[0];
    const float* Wih0 = (const float*)d_in[1];
    const float* Whh0 = (const float*)d_in[2];
    const float* bih0 = (const float*)d_in[3];
    const float* bhh0 = (const float*)d_in[4];
    const float* Wih1 = (const float*)d_in[5];
    const float* Whh1 = (const float*)d_in[6];
    const float* bih1 = (const float*)d_in[7];
    const float* bhh1 = (const float*)d_in[8];
    const float* W1   = (const float*)d_in[9];
    const float* b1   = (const float*)d_in[10];
    const float* W2   = (const float*)d_in[11];
    const float* b2   = (const float*)d_in[12];

    int B = out_size / T_LEN;                 // output is [B, T, 1]
    int grid = (B + QPB - 1) / QPB;           // 128 blocks for B=4096
    lstm_pipe_kernel<<<grid, BLOCKT>>>(x, Wih0, Whh0, bih0, bhh0,
                                       Wih1, Whh1, bih1, bhh1,
                                       W1, b1, W2, b2,
                                       (float*)d_out, B);
}